// round 1
// baseline (speedup 1.0000x reference)
#include <cuda_runtime.h>
#include <math.h>

#define S_LEN 4096
#define D_MODEL 1024
#define N_HEADS 16
#define D_HEAD 64

// Scratch (allocation-free rule: __device__ globals)
__device__ float g_Qp[S_LEN * D_MODEL];
__device__ float g_Kp[S_LEN * D_MODEL];
__device__ float g_Vp[S_LEN * D_MODEL];
__device__ float g_vals[S_LEN * D_MODEL];
// Fallback attn storage if the harness output does not include attn
__device__ float g_attn_fallback[(size_t)N_HEADS * S_LEN * S_LEN];

// ---------------------------------------------------------------------------
// Register-tiled GEMM: C = alpha * (A @ B) [+ bias]
//  NT=false: B is row-major [K, N] (ldb = row stride)
//  NT=true : B is row-major [N, K] (dot of A rows with B rows) -> C = A @ B^T
// Batched via blockIdx.z with element-offset strides (lets us use a column
// offset of h*64 as a "batch stride" inside a row-major [*,1024] matrix).
// Tiles: BM=BN=64, BK=16, 256 threads, 4x4 accum per thread.
// ---------------------------------------------------------------------------
template <bool NT>
__global__ void gemm_kernel(const float* __restrict__ A, int lda, long strideA,
                            const float* __restrict__ B, int ldb, long strideB,
                            float* __restrict__ C, int ldc, long strideC,
                            int M, int N, int K,
                            const float* __restrict__ bias, float alpha)
{
    const int BM = 64, BN = 64, BK = 16;
    __shared__ __align__(16) float As[BK][BM];
    __shared__ __align__(16) float Bs[BK][BN];

    long b = blockIdx.z;
    A += b * strideA;
    B += b * strideB;
    C += b * strideC;

    int m0 = blockIdx.y * BM;
    int n0 = blockIdx.x * BN;
    int tid = threadIdx.x;        // 0..255
    int tx = tid & 15;            // 0..15 -> 4 output cols each
    int ty = tid >> 4;            // 0..15 -> 4 output rows each

    float acc[4][4] = {};

    for (int k0 = 0; k0 < K; k0 += BK) {
        // Load A tile transposed into As[k][m] (coalesced along k)
        {
            int kk = tid & 15;
            int mm = tid >> 4;
            #pragma unroll
            for (int s = 0; s < 4; s++)
                As[kk][mm + s * 16] =
                    A[(long)(m0 + mm + s * 16) * lda + (k0 + kk)];
        }
        // Load B tile into Bs[k][n]
        if (!NT) {
            int nn = tid & 63;
            int kk = tid >> 6;
            #pragma unroll
            for (int s = 0; s < 4; s++)
                Bs[kk + s * 4][nn] =
                    B[(long)(k0 + kk + s * 4) * ldb + (n0 + nn)];
        } else {
            int kk = tid & 15;
            int nn = tid >> 4;
            #pragma unroll
            for (int s = 0; s < 4; s++)
                Bs[kk][nn + s * 16] =
                    B[(long)(n0 + nn + s * 16) * ldb + (k0 + kk)];
        }
        __syncthreads();

        #pragma unroll
        for (int kk = 0; kk < BK; kk++) {
            float4 a4 = *(const float4*)(&As[kk][ty * 4]);
            float4 b4 = *(const float4*)(&Bs[kk][tx * 4]);
            float ar[4] = {a4.x, a4.y, a4.z, a4.w};
            float br[4] = {b4.x, b4.y, b4.z, b4.w};
            #pragma unroll
            for (int i = 0; i < 4; i++)
                #pragma unroll
                for (int j = 0; j < 4; j++)
                    acc[i][j] = fmaf(ar[i], br[j], acc[i][j]);
        }
        __syncthreads();
    }

    #pragma unroll
    for (int i = 0; i < 4; i++) {
        int m = m0 + ty * 4 + i;
        #pragma unroll
        for (int j = 0; j < 4; j++) {
            int n = n0 + tx * 4 + j;
            float v = alpha * acc[i][j];
            if (bias) v += bias[n];
            C[(long)m * ldc + n] = v;
        }
    }
}

// ---------------------------------------------------------------------------
// Row softmax over rows of length 4096, in place.
// One block of 256 threads per row; 16 values per thread kept in registers
// so the row is read from HBM once and written once.
// ---------------------------------------------------------------------------
__global__ void softmax_kernel(float* __restrict__ attn)
{
    long row = blockIdx.x;                  // h*S + q
    float* p = attn + row * (long)S_LEN;
    int tid = threadIdx.x;

    float vals[16];
    float mx = -INFINITY;
    #pragma unroll
    for (int i = 0; i < 16; i++) {
        vals[i] = p[tid + i * 256];
        mx = fmaxf(mx, vals[i]);
    }

    __shared__ float red[256];
    red[tid] = mx;
    __syncthreads();
    #pragma unroll
    for (int s = 128; s > 0; s >>= 1) {
        if (tid < s) red[tid] = fmaxf(red[tid], red[tid + s]);
        __syncthreads();
    }
    mx = red[0];
    __syncthreads();

    float sum = 0.f;
    #pragma unroll
    for (int i = 0; i < 16; i++) {
        vals[i] = expf(vals[i] - mx);
        sum += vals[i];
    }
    red[tid] = sum;
    __syncthreads();
    #pragma unroll
    for (int s = 128; s > 0; s >>= 1) {
        if (tid < s) red[tid] += red[tid + s];
        __syncthreads();
    }
    float inv = 1.0f / red[0];

    #pragma unroll
    for (int i = 0; i < 16; i++)
        p[tid + i * 256] = vals[i] * inv;
}

extern "C" void kernel_launch(void* const* d_in, const int* in_sizes, int n_in,
                              void* d_out, int out_size)
{
    const float* q  = (const float*)d_in[0];
    const float* k  = (const float*)d_in[1];
    const float* v  = (const float*)d_in[2];
    const float* Wq = (const float*)d_in[3];
    const float* bq = (const float*)d_in[4];
    const float* Wk = (const float*)d_in[5];
    const float* bk = (const float*)d_in[6];
    const float* Wv = (const float*)d_in[7];
    const float* bv = (const float*)d_in[8];
    const float* Wo = (const float*)d_in[9];
    const float* bo = (const float*)d_in[10];

    float* out = (float*)d_out;

    // Scratch pointers via symbol lookup (no allocation)
    float *Qp, *Kp, *Vp, *Vals, *attn_fb;
    cudaGetSymbolAddress((void**)&Qp,   g_Qp);
    cudaGetSymbolAddress((void**)&Kp,   g_Kp);
    cudaGetSymbolAddress((void**)&Vp,   g_Vp);
    cudaGetSymbolAddress((void**)&Vals, g_vals);
    cudaGetSymbolAddress((void**)&attn_fb, g_attn_fallback);

    const long OUT_ELEMS  = (long)S_LEN * D_MODEL;
    const long ATTN_ELEMS = (long)N_HEADS * S_LEN * S_LEN;

    // Output tuple is (out, attn); fall back to scratch if attn isn't in d_out.
    float* attn = ((long)out_size >= OUT_ELEMS + ATTN_ELEMS)
                      ? (out + OUT_ELEMS)
                      : attn_fb;

    dim3 blk(256);
    const float scale = 1.0f / sqrtf((float)D_HEAD);

    // 1) Projections: P = x @ W + b   (M=4096, N=1024, K=1024)
    dim3 gProj(D_MODEL / 64, S_LEN / 64, 1);
    gemm_kernel<false><<<gProj, blk>>>(q, D_MODEL, 0, Wq, D_MODEL, 0,
                                       Qp, D_MODEL, 0,
                                       S_LEN, D_MODEL, D_MODEL, bq, 1.0f);
    gemm_kernel<false><<<gProj, blk>>>(k, D_MODEL, 0, Wk, D_MODEL, 0,
                                       Kp, D_MODEL, 0,
                                       S_LEN, D_MODEL, D_MODEL, bk, 1.0f);
    gemm_kernel<false><<<gProj, blk>>>(v, D_MODEL, 0, Wv, D_MODEL, 0,
                                       Vp, D_MODEL, 0,
                                       S_LEN, D_MODEL, D_MODEL, bv, 1.0f);

    // 2) Scores: attn[h] = scale * Qh @ Kh^T   (per head: M=N=4096, K=64)
    //    Head selected by column offset h*64 via "batch stride" 64.
    dim3 gScore(S_LEN / 64, S_LEN / 64, N_HEADS);
    gemm_kernel<true><<<gScore, blk>>>(Qp, D_MODEL, D_HEAD,
                                       Kp, D_MODEL, D_HEAD,
                                       attn, S_LEN, (long)S_LEN * S_LEN,
                                       S_LEN, S_LEN, D_HEAD, nullptr, scale);

    // 3) Softmax over last dim, in place
    softmax_kernel<<<N_HEADS * S_LEN, 256>>>(attn);

    // 4) vals: C[s, h*64+d] = attn[h] @ Vh   (per head: M=4096, N=64, K=4096)
    //    C layout equals the concatenated [S, D_MODEL] directly.
    dim3 gAV(1, S_LEN / 64, N_HEADS);
    gemm_kernel<false><<<gAV, blk>>>(attn, S_LEN, (long)S_LEN * S_LEN,
                                     Vp, D_MODEL, D_HEAD,
                                     Vals, D_MODEL, D_HEAD,
                                     S_LEN, D_HEAD, S_LEN, nullptr, 1.0f);

    // 5) Output projection: out = vals @ Wo + bo
    gemm_kernel<false><<<gProj, blk>>>(Vals, D_MODEL, 0, Wo, D_MODEL, 0,
                                       out, D_MODEL, 0,
                                       S_LEN, D_MODEL, D_MODEL, bo, 1.0f);
}

// round 2
// speedup vs baseline: 3.5055x; 3.5055x over previous
#include <cuda_runtime.h>
#include <math.h>
#include <stdint.h>

#define S_LEN 4096
#define D_MODEL 1024
#define N_HEADS 16
#define D_HEAD 64
#define BK 32

// Scratch (allocation-free rule: __device__ globals)
__device__ float g_Qp[S_LEN * D_MODEL];
__device__ float g_Kp[S_LEN * D_MODEL];
__device__ float g_Vp[S_LEN * D_MODEL];
__device__ float g_vals[S_LEN * D_MODEL];
__device__ float g_attn_fallback[(size_t)N_HEADS * S_LEN * S_LEN];

__device__ __forceinline__ float to_tf32(float x) {
    float y;
    asm("cvt.rna.tf32.f32 %0, %1;" : "=f"(y) : "f"(x));
    return y;
}

__device__ __forceinline__ void mma_tf32(float& d0, float& d1, float& d2, float& d3,
                                         float a0, float a1, float a2, float a3,
                                         float b0, float b1)
{
    uint32_t ua0 = __float_as_uint(a0), ua1 = __float_as_uint(a1);
    uint32_t ua2 = __float_as_uint(a2), ua3 = __float_as_uint(a3);
    uint32_t ub0 = __float_as_uint(b0), ub1 = __float_as_uint(b1);
    asm volatile(
        "mma.sync.aligned.m16n8k8.row.col.f32.tf32.tf32.f32 "
        "{%0,%1,%2,%3}, {%4,%5,%6,%7}, {%8,%9}, {%0,%1,%2,%3};"
        : "+f"(d0), "+f"(d1), "+f"(d2), "+f"(d3)
        : "r"(ua0), "r"(ua1), "r"(ua2), "r"(ua3), "r"(ub0), "r"(ub1));
}

// ---------------------------------------------------------------------------
// TF32 tensor-core GEMM: C = alpha * (A @ op(B)) [+ bias]
//  NT=false: B row-major [K, N]   -> C = A @ B
//  NT=true : B row-major [N, K]   -> C = A @ B^T
// BM x BN tile, BK=32, 256 threads (8 warps, each 32 x BN/2).
// A/B tiles stored tf32-rounded in smem. Batched via blockIdx.z strides.
// ---------------------------------------------------------------------------
template <int BM, int BN, bool NT>
__global__ void __launch_bounds__(256, 2)
mma_gemm(const float* __restrict__ A, int lda, long strideA,
         const float* __restrict__ B, int ldb, long strideB,
         float* __restrict__ C, int ldc, long strideC,
         int K, const float* __restrict__ bias, float alpha)
{
    __shared__ __align__(16) float As[BM][BK + 4];
    __shared__ __align__(16) float Bs[NT ? BN : BK][NT ? (BK + 4) : (BN + 4)];

    const long b = blockIdx.z;
    A += b * strideA;
    B += b * strideB;
    C += b * strideC;

    const int m0 = blockIdx.y * BM;
    const int n0 = blockIdx.x * BN;
    const int tid = threadIdx.x;
    const int warp = tid >> 5;
    const int lane = tid & 31;
    const int gid = lane >> 2;     // groupID
    const int tig = lane & 3;      // threadID in group

    const int WN = BN / 2;
    const int wm0 = (warp >> 1) * 32;      // 4 warps along M
    const int wn0 = (warp & 1) * WN;       // 2 warps along N

    float acc[2][BN / 16][4];              // [mi][ni][4], ni < WN/8 = BN/16
    #pragma unroll
    for (int mi = 0; mi < 2; mi++)
        #pragma unroll
        for (int ni = 0; ni < BN / 16; ni++)
            #pragma unroll
            for (int j = 0; j < 4; j++) acc[mi][ni][j] = 0.f;

    for (long k0 = 0; k0 < K; k0 += BK) {
        // ---- A tile: [BM][BK], float4 along k ----
        #pragma unroll
        for (int i = 0; i < BM / 32; i++) {
            int idx = tid + i * 256;
            int r = idx >> 3;
            int kq = (idx & 7) * 4;
            float4 f = *(const float4*)(A + (long)(m0 + r) * lda + k0 + kq);
            float4 t = make_float4(to_tf32(f.x), to_tf32(f.y), to_tf32(f.z), to_tf32(f.w));
            *(float4*)&As[r][kq] = t;
        }
        // ---- B tile ----
        if (NT) {
            // B[N,K]: rows n, float4 along k -> Bs[n][k]
            #pragma unroll
            for (int i = 0; i < BN / 32; i++) {
                int idx = tid + i * 256;
                int r = idx >> 3;
                int kq = (idx & 7) * 4;
                float4 f = *(const float4*)(B + (long)(n0 + r) * ldb + k0 + kq);
                float4 t = make_float4(to_tf32(f.x), to_tf32(f.y), to_tf32(f.z), to_tf32(f.w));
                *(float4*)&Bs[r][kq] = t;
            }
        } else {
            // B[K,N]: rows k, float4 along n -> Bs[k][n]
            #pragma unroll
            for (int i = 0; i < BN / 32; i++) {
                int idx = tid + i * 256;
                int kr = idx / (BN / 4);
                int nq = (idx % (BN / 4)) * 4;
                float4 f = *(const float4*)(B + (long)(k0 + kr) * ldb + n0 + nq);
                float4 t = make_float4(to_tf32(f.x), to_tf32(f.y), to_tf32(f.z), to_tf32(f.w));
                *(float4*)&Bs[kr][nq] = t;
            }
        }
        __syncthreads();

        #pragma unroll
        for (int ks = 0; ks < BK; ks += 8) {
            float af[2][4];
            #pragma unroll
            for (int mi = 0; mi < 2; mi++) {
                af[mi][0] = As[wm0 + mi * 16 + gid][ks + tig];
                af[mi][1] = As[wm0 + mi * 16 + gid + 8][ks + tig];
                af[mi][2] = As[wm0 + mi * 16 + gid][ks + tig + 4];
                af[mi][3] = As[wm0 + mi * 16 + gid + 8][ks + tig + 4];
            }
            float bf[BN / 16][2];
            #pragma unroll
            for (int ni = 0; ni < BN / 16; ni++) {
                if (NT) {
                    bf[ni][0] = Bs[wn0 + ni * 8 + gid][ks + tig];
                    bf[ni][1] = Bs[wn0 + ni * 8 + gid][ks + tig + 4];
                } else {
                    bf[ni][0] = Bs[ks + tig][wn0 + ni * 8 + gid];
                    bf[ni][1] = Bs[ks + tig + 4][wn0 + ni * 8 + gid];
                }
            }
            #pragma unroll
            for (int mi = 0; mi < 2; mi++)
                #pragma unroll
                for (int ni = 0; ni < BN / 16; ni++)
                    mma_tf32(acc[mi][ni][0], acc[mi][ni][1], acc[mi][ni][2], acc[mi][ni][3],
                             af[mi][0], af[mi][1], af[mi][2], af[mi][3],
                             bf[ni][0], bf[ni][1]);
        }
        __syncthreads();
    }

    // ---- Epilogue ----
    #pragma unroll
    for (int mi = 0; mi < 2; mi++) {
        int r0 = m0 + wm0 + mi * 16 + gid;
        #pragma unroll
        for (int ni = 0; ni < BN / 16; ni++) {
            int c = n0 + wn0 + ni * 8 + tig * 2;
            float bv0 = bias ? bias[c] : 0.f;
            float bv1 = bias ? bias[c + 1] : 0.f;
            float2 v0 = make_float2(alpha * acc[mi][ni][0] + bv0,
                                    alpha * acc[mi][ni][1] + bv1);
            float2 v1 = make_float2(alpha * acc[mi][ni][2] + bv0,
                                    alpha * acc[mi][ni][3] + bv1);
            *(float2*)&C[(long)r0 * ldc + c] = v0;
            *(float2*)&C[(long)(r0 + 8) * ldc + c] = v1;
        }
    }
}

// ---------------------------------------------------------------------------
// Row softmax, rows of 4096, in place. 256 threads/row, float4 IO.
// ---------------------------------------------------------------------------
__global__ void softmax_kernel(float* __restrict__ attn)
{
    long row = blockIdx.x;
    float4* p = (float4*)(attn + row * (long)S_LEN);
    int tid = threadIdx.x;
    int warp = tid >> 5, lane = tid & 31;

    float4 v[4];
    float mx = -INFINITY;
    #pragma unroll
    for (int j = 0; j < 4; j++) {
        v[j] = p[tid + j * 256];
        mx = fmaxf(mx, fmaxf(fmaxf(v[j].x, v[j].y), fmaxf(v[j].z, v[j].w)));
    }

    __shared__ float red[8];
    #pragma unroll
    for (int off = 16; off > 0; off >>= 1)
        mx = fmaxf(mx, __shfl_xor_sync(0xffffffffu, mx, off));
    if (lane == 0) red[warp] = mx;
    __syncthreads();
    mx = red[0];
    #pragma unroll
    for (int w = 1; w < 8; w++) mx = fmaxf(mx, red[w]);
    __syncthreads();

    float sum = 0.f;
    #pragma unroll
    for (int j = 0; j < 4; j++) {
        v[j].x = __expf(v[j].x - mx); v[j].y = __expf(v[j].y - mx);
        v[j].z = __expf(v[j].z - mx); v[j].w = __expf(v[j].w - mx);
        sum += v[j].x + v[j].y + v[j].z + v[j].w;
    }
    #pragma unroll
    for (int off = 16; off > 0; off >>= 1)
        sum += __shfl_xor_sync(0xffffffffu, sum, off);
    if (lane == 0) red[warp] = sum;
    __syncthreads();
    sum = 0.f;
    #pragma unroll
    for (int w = 0; w < 8; w++) sum += red[w];
    float inv = 1.0f / sum;

    #pragma unroll
    for (int j = 0; j < 4; j++) {
        v[j].x *= inv; v[j].y *= inv; v[j].z *= inv; v[j].w *= inv;
        p[tid + j * 256] = v[j];
    }
}

extern "C" void kernel_launch(void* const* d_in, const int* in_sizes, int n_in,
                              void* d_out, int out_size)
{
    const float* q  = (const float*)d_in[0];
    const float* k  = (const float*)d_in[1];
    const float* v  = (const float*)d_in[2];
    const float* Wq = (const float*)d_in[3];
    const float* bq = (const float*)d_in[4];
    const float* Wk = (const float*)d_in[5];
    const float* bk = (const float*)d_in[6];
    const float* Wv = (const float*)d_in[7];
    const float* bv = (const float*)d_in[8];
    const float* Wo = (const float*)d_in[9];
    const float* bo = (const float*)d_in[10];

    float* out = (float*)d_out;

    float *Qp, *Kp, *Vp, *Vals, *attn_fb;
    cudaGetSymbolAddress((void**)&Qp,   g_Qp);
    cudaGetSymbolAddress((void**)&Kp,   g_Kp);
    cudaGetSymbolAddress((void**)&Vp,   g_Vp);
    cudaGetSymbolAddress((void**)&Vals, g_vals);
    cudaGetSymbolAddress((void**)&attn_fb, g_attn_fallback);

    const long OUT_ELEMS  = (long)S_LEN * D_MODEL;
    const long ATTN_ELEMS = (long)N_HEADS * S_LEN * S_LEN;
    float* attn = ((long)out_size >= OUT_ELEMS + ATTN_ELEMS)
                      ? (out + OUT_ELEMS)
                      : attn_fb;

    dim3 blk(256);
    const float scale = 1.0f / sqrtf((float)D_HEAD);

    // 1) Projections: P = x @ W + b  (M=4096, N=1024, K=1024)
    dim3 gProj(D_MODEL / 128, S_LEN / 128, 1);
    mma_gemm<128, 128, false><<<gProj, blk>>>(q, D_MODEL, 0, Wq, D_MODEL, 0,
                                              Qp, D_MODEL, 0,
                                              D_MODEL, bq, 1.0f);
    mma_gemm<128, 128, false><<<gProj, blk>>>(k, D_MODEL, 0, Wk, D_MODEL, 0,
                                              Kp, D_MODEL, 0,
                                              D_MODEL, bk, 1.0f);
    mma_gemm<128, 128, false><<<gProj, blk>>>(v, D_MODEL, 0, Wv, D_MODEL, 0,
                                              Vp, D_MODEL, 0,
                                              D_MODEL, bv, 1.0f);

    // 2) Scores: attn[h] = scale * Qh @ Kh^T   (M=N=4096, K=64 per head)
    dim3 gScore(S_LEN / 128, S_LEN / 128, N_HEADS);
    mma_gemm<128, 128, true><<<gScore, blk>>>(Qp, D_MODEL, D_HEAD,
                                              Kp, D_MODEL, D_HEAD,
                                              attn, S_LEN, (long)S_LEN * S_LEN,
                                              D_HEAD, nullptr, scale);

    // 3) Softmax
    softmax_kernel<<<N_HEADS * S_LEN, 256>>>(attn);

    // 4) vals[s, h*64+d] = attn[h] @ Vh   (M=4096, N=64, K=4096 per head)
    dim3 gAV(1, S_LEN / 128, N_HEADS);
    mma_gemm<128, 64, false><<<gAV, blk>>>(attn, S_LEN, (long)S_LEN * S_LEN,
                                           Vp, D_MODEL, D_HEAD,
                                           Vals, D_MODEL, D_HEAD,
                                           S_LEN, nullptr, 1.0f);

    // 5) out = vals @ Wo + bo
    mma_gemm<128, 128, false><<<gProj, blk>>>(Vals, D_MODEL, 0, Wo, D_MODEL, 0,
                                              out, D_MODEL, 0,
                                              D_MODEL, bo, 1.0f);
}